// round 3
// baseline (speedup 1.0000x reference)
#include <cuda_runtime.h>
#include <cstdint>

// ====================== helpers ======================
__device__ __forceinline__ uint32_t smem_u32(const void* p) {
    uint32_t a;
    asm("{ .reg .u64 t; cvta.to.shared.u64 t, %1; cvt.u32.u64 %0, t; }" : "=r"(a) : "l"(p));
    return a;
}
__device__ __forceinline__ void ldsm_x4(uint32_t* d, uint32_t addr) {
    asm volatile("ldmatrix.sync.aligned.m8n8.x4.shared.b16 {%0,%1,%2,%3}, [%4];"
        : "=r"(d[0]), "=r"(d[1]), "=r"(d[2]), "=r"(d[3]) : "r"(addr));
}
__device__ __forceinline__ void mma_s8(int* c, const uint32_t* a, uint32_t b0, uint32_t b1) {
    asm volatile(
        "mma.sync.aligned.m16n8k32.row.col.s32.s8.s8.s32 "
        "{%0,%1,%2,%3}, {%4,%5,%6,%7}, {%8,%9}, {%0,%1,%2,%3};"
        : "+r"(c[0]), "+r"(c[1]), "+r"(c[2]), "+r"(c[3])
        : "r"(a[0]), "r"(a[1]), "r"(a[2]), "r"(a[3]), "r"(b0), "r"(b1));
}
__device__ __forceinline__ uint32_t pack4(int i0, int i1, int i2, int i3) {
    uint32_t t0 = __byte_perm((uint32_t)i0, (uint32_t)i1, 0x0040);
    uint32_t t1 = __byte_perm((uint32_t)i2, (uint32_t)i3, 0x0040);
    return __byte_perm(t0, t1, 0x5410);
}

// ====================== weight digit planes (converted once) ======================
// layout: plane p, row n (0..63), 128 int8 along k; 16B chunks XOR-swizzled by (n&7)
__device__ unsigned char g_Bplanes[2][64 * 128];

__global__ void prep_weight_kernel(const float* __restrict__ weight) {
    for (int idx = threadIdx.x; idx < 8192; idx += 256) {
        int n = idx >> 7, k = idx & 127;
        float v = weight[k * 64 + n] * 65536.0f;             // sw = 2^-16
        float b0f = rintf(v * 0.0078125f);
        b0f = fminf(fmaxf(b0f, -127.0f), 127.0f);
        float b1f = rintf(fmaf(b0f, -128.0f, v));
        int off = n * 128 + (((k >> 4) ^ (n & 7)) << 4) + (k & 15);
        g_Bplanes[0][off] = (unsigned char)(int)b0f;
        g_Bplanes[1][off] = (unsigned char)(int)b1f;
    }
}

// ====================== smem layout (bytes) ======================
// A0: 64x128 int8 @ 0       (8192)
// A1: 64x128 int8 @ 8192    (8192)
// B0: 64x128 int8 @ 16384   (8192)
// B1: 64x128 int8 @ 24576   (8192)
// w : 16 blocks x 16 fp32 @ 32768 (1024)
// bias: 64 fp32 @ 33792 (256)
// H (epilogue): 64 x 68 fp32 @ 0 (17408) — overlays A planes + 1KB of B0 (dead)
#define SM_A0   0u
#define SM_A1   8192u
#define SM_B0   16384u
#define SM_W    32768u
#define SM_BIAS 33792u
#define SMEM_TOTAL 34048
#define SM_H    0u
#define H_STRIDE 68

__global__ void __launch_bounds__(128, 4) gcn_int8_kernel(
    const float* __restrict__ feat,
    const float* __restrict__ w,
    const float* __restrict__ bias,
    const float* __restrict__ alpha_p,
    float* __restrict__ out,
    int n_pool_blocks)
{
    extern __shared__ unsigned char s_raw[];
    const uint32_t sb = smem_u32(s_raw);
    const int tid = threadIdx.x;
    const int wid = tid >> 5;
    const int lid = tid & 31;

    const float alpha = __ldg(alpha_p);

    // ---------- B planes: straight copy from pre-converted global (16KB) ----------
    {
        const uint4* gb = (const uint4*)&g_Bplanes[0][0];
        uint4* sp = (uint4*)(s_raw + SM_B0);
        #pragma unroll
        for (int i = 0; i < 8; ++i) sp[tid + i * 128] = gb[tid + i * 128];
    }

    // ---------- feat tile: 64 rows x 128 fp32 -> int8 digit planes ----------
    {
        const float4* fp = (const float4*)(feat + (size_t)blockIdx.x * (64 * 128));
        #pragma unroll
        for (int it = 0; it < 16; ++it) {
            int g  = tid + it * 128;        // float4 index 0..2047
            int r  = g >> 5;                // row 0..63
            int c4 = g & 31;                // float4 within row
            float4 v = fp[g];
            float s0 = v.x * 2048.0f, s1 = v.y * 2048.0f;   // sx = 2^-11
            float s2 = v.z * 2048.0f, s3 = v.w * 2048.0f;
            float h0 = fminf(fmaxf(rintf(s0 * 0.0078125f), -127.f), 127.f);
            float h1 = fminf(fmaxf(rintf(s1 * 0.0078125f), -127.f), 127.f);
            float h2 = fminf(fmaxf(rintf(s2 * 0.0078125f), -127.f), 127.f);
            float h3 = fminf(fmaxf(rintf(s3 * 0.0078125f), -127.f), 127.f);
            int l0 = (int)rintf(fmaf(h0, -128.f, s0));
            int l1 = (int)rintf(fmaf(h1, -128.f, s1));
            int l2 = (int)rintf(fmaf(h2, -128.f, s2));
            int l3 = (int)rintf(fmaf(h3, -128.f, s3));
            uint32_t u0 = pack4((int)h0, (int)h1, (int)h2, (int)h3);
            uint32_t u1 = pack4(l0, l1, l2, l3);
            uint32_t off = (uint32_t)r * 128u
                         + (uint32_t)((((c4 >> 2) ^ (r & 7)) << 4) + ((c4 & 3) << 2));
            *(uint32_t*)(s_raw + SM_A0 + off) = u0;
            *(uint32_t*)(s_raw + SM_A1 + off) = u1;
        }
    }

    // ---------- edge weights (16 blocks x 16 fp32) + bias ----------
    {
        if (tid < 64)  ((uint4*)(s_raw + SM_W))[tid] =
            ((const uint4*)(w + (size_t)blockIdx.x * 256))[tid];
        if (tid < 16)  ((uint4*)(s_raw + SM_BIAS))[tid] = ((const uint4*)bias)[tid];
    }
    __syncthreads();

    // ---------- IMMA: warp tile 32(M) x 32(N), K = 4 segs x 128 ----------
    float accf[8][4];
    #pragma unroll
    for (int t = 0; t < 8; ++t)
        #pragma unroll
        for (int i = 0; i < 4; ++i) accf[t][i] = 0.f;

    const int warpRow = (wid & 1) << 5;
    const int warpCol = (wid >> 1) << 5;
    {
        const int aRow = warpRow + (lid & 15);
        const int aS   = aRow & 7;
        const uint32_t aOff = sb + (uint32_t)aRow * 128u;      // + plane base later
        const int bn   = warpCol + (lid & 15);
        const int bS   = bn & 7;
        const uint32_t bOff = sb + SM_B0 + (uint32_t)bn * 128u;
        const int cSel = lid >> 4;                             // 0/1 chunk select

        const float segscale[4] = { 1.0f / 8192.0f,            // a0*b0 : 2^-27 * 2^14
                                    1.0f / 1048576.0f,         // a0*b1 : 2^-20
                                    1.0f / 1048576.0f,         // a1*b0 : 2^-20
                                    1.0f / 134217728.0f };     // a1*b1 : 2^-27

        #pragma unroll
        for (int seg = 0; seg < 4; ++seg) {
            const uint32_t Ab = aOff + ((seg >> 1) ? (SM_A1) : (SM_A0));
            const uint32_t Bb = bOff + ((seg & 1) ? 8192u : 0u);
            int acci[8][4];
            #pragma unroll
            for (int t = 0; t < 8; ++t)
                #pragma unroll
                for (int i = 0; i < 4; ++i) acci[t][i] = 0;

            #pragma unroll
            for (int ks = 0; ks < 4; ++ks) {
                const uint32_t aCh = (uint32_t)((((ks << 1) + cSel) ^ aS) << 4);
                const uint32_t bCh = (uint32_t)((((ks << 1) + cSel) ^ bS) << 4);
                uint32_t a0[4], a1[4], b0[4], b1[4];
                ldsm_x4(a0, Ab + aCh);                 // rows warpRow..+15
                ldsm_x4(a1, Ab + 2048u + aCh);         // rows +16..+31
                ldsm_x4(b0, Bb + bCh);                 // n warpCol..+15
                ldsm_x4(b1, Bb + 2048u + bCh);         // n +16..+31
                #pragma unroll
                for (int mt = 0; mt < 2; ++mt) {
                    const uint32_t* af = mt ? a1 : a0;
                    mma_s8(acci[mt * 4 + 0], af, b0[0], b0[2]);
                    mma_s8(acci[mt * 4 + 1], af, b0[1], b0[3]);
                    mma_s8(acci[mt * 4 + 2], af, b1[0], b1[2]);
                    mma_s8(acci[mt * 4 + 3], af, b1[1], b1[3]);
                }
            }
            const float sc = segscale[seg];
            #pragma unroll
            for (int t = 0; t < 8; ++t)
                #pragma unroll
                for (int i = 0; i < 4; ++i)
                    accf[t][i] = fmaf(sc, (float)acci[t][i], accf[t][i]);
        }
    }

    __syncthreads();   // all warps done with A/B smem; safe to overlay H

    // ---------- accumulators -> smem H[64][64] (stride 68) ----------
    {
        float* Hp = (float*)(s_raw + SM_H);
        const int rr = lid >> 2;
        const int cc = (lid & 3) << 1;
        #pragma unroll
        for (int mt = 0; mt < 2; ++mt) {
            const int row = warpRow + mt * 16 + rr;
            #pragma unroll
            for (int no = 0; no < 4; ++no) {
                const int col = warpCol + no * 8 + cc;
                const float* a = accf[mt * 4 + no];
                *(float2*)(Hp + (size_t)row * H_STRIDE + col)       = make_float2(a[0], a[1]);
                *(float2*)(Hp + (size_t)(row + 8) * H_STRIDE + col) = make_float2(a[2], a[3]);
            }
        }
    }
    __syncthreads();

    // ---------- epilogue: 16 node-blocks x 8 threads (8 cols/thread) ----------
    {
        const int tb = tid >> 3;                   // node-block 0..15
        const int q  = tid & 7;
        const int c0 = q << 3;
        const float* Hb = (const float*)(s_raw + SM_H);
        const float* ws = (const float*)(s_raw + SM_W) + tb * 16;
        const float* bs = (const float*)(s_raw + SM_BIAS);

        float a0[8], h1[8], h2[8], h3[8], bb[8];
        const float* r0p = Hb + (size_t)(4 * tb    ) * H_STRIDE + c0;
        const float* r1p = Hb + (size_t)(4 * tb + 1) * H_STRIDE + c0;
        const float* r2p = Hb + (size_t)(4 * tb + 2) * H_STRIDE + c0;
        const float* r3p = Hb + (size_t)(4 * tb + 3) * H_STRIDE + c0;
        *(float4*)(a0) = *(const float4*)(r0p); *(float4*)(a0 + 4) = *(const float4*)(r0p + 4);
        *(float4*)(h1) = *(const float4*)(r1p); *(float4*)(h1 + 4) = *(const float4*)(r1p + 4);
        *(float4*)(h2) = *(const float4*)(r2p); *(float4*)(h2 + 4) = *(const float4*)(r2p + 4);
        *(float4*)(h3) = *(const float4*)(r3p); *(float4*)(h3 + 4) = *(const float4*)(r3p + 4);
        *(float4*)(bb) = *(const float4*)(bs + c0); *(float4*)(bb + 4) = *(const float4*)(bs + c0 + 4);

        float pool[8];
        #pragma unroll
        for (int c = 0; c < 8; ++c) pool[c] = 0.f;
        #pragma unroll
        for (int j = 0; j < 4; ++j) {
            float w1 = ws[4 + j], w2 = ws[8 + j], w3 = ws[12 + j];
            #pragma unroll
            for (int c = 0; c < 8; ++c) {
                float hv = fmaf(w1, h1[c], fmaf(w2, h2[c], w3 * h3[c])) + bb[c];
                hv = (hv >= 0.f) ? hv : alpha * hv;
                pool[c] += hv;
            }
        }
        float pn = 0.f, an = 0.f;
        float aa[8];
        #pragma unroll
        for (int c = 0; c < 8; ++c) {
            pool[c] *= 0.25f;
            pn = fmaf(pool[c], pool[c], pn);
            float x = a0[c] + bb[c];
            x = (x >= 0.f) ? x : alpha * x;
            aa[c] = x;
            an = fmaf(x, x, an);
        }
        #pragma unroll
        for (int o = 1; o < 8; o <<= 1) {
            pn += __shfl_xor_sync(0xFFFFFFFFu, pn, o);
            an += __shfl_xor_sync(0xFFFFFFFFu, an, o);
        }
        float pinv = 1.f / fmaxf(sqrtf(pn), 1e-12f);
        float ainv = 1.f / fmaxf(sqrtf(an), 1e-12f);

        size_t gb = (size_t)blockIdx.x * 16 + tb;
        float* po = out + gb * 64 + c0;
        float* ao = out + (size_t)n_pool_blocks * 64 + gb * 64 + c0;
        *(float4*)(po)     = make_float4(pool[0]*pinv, pool[1]*pinv, pool[2]*pinv, pool[3]*pinv);
        *(float4*)(po + 4) = make_float4(pool[4]*pinv, pool[5]*pinv, pool[6]*pinv, pool[7]*pinv);
        *(float4*)(ao)     = make_float4(aa[0]*ainv, aa[1]*ainv, aa[2]*ainv, aa[3]*ainv);
        *(float4*)(ao + 4) = make_float4(aa[4]*ainv, aa[5]*ainv, aa[6]*ainv, aa[7]*ainv);
    }
}

extern "C" void kernel_launch(void* const* d_in, const int* in_sizes, int n_in,
                              void* d_out, int out_size) {
    const float* feat   = (const float*)d_in[0];
    const float* w      = (const float*)d_in[1];
    const float* weight = (const float*)d_in[2];
    const float* bias   = (const float*)d_in[3];
    const float* alpha  = (const float*)d_in[4];
    float* out = (float*)d_out;

    int n_nodes = in_sizes[0] / 128;       // N = 524288
    int n_blk   = n_nodes / 4;             // B = 131072
    int grid    = n_nodes / 64;            // 8192 CTAs (64 rows each)

    prep_weight_kernel<<<1, 256>>>(weight);

    cudaFuncSetAttribute(gcn_int8_kernel,
                         cudaFuncAttributeMaxDynamicSharedMemorySize, SMEM_TOTAL);
    gcn_int8_kernel<<<grid, 128, SMEM_TOTAL>>>(feat, w, bias, alpha, out, n_blk);
}

// round 4
// speedup vs baseline: 2.7637x; 2.7637x over previous
#include <cuda_runtime.h>
#include <cuda_fp16.h>
#include <cstdint>

// ====================== helpers ======================
__device__ __forceinline__ uint32_t smem_u32(const void* p) {
    uint32_t a;
    asm("{ .reg .u64 t; cvta.to.shared.u64 t, %1; cvt.u32.u64 %0, t; }" : "=r"(a) : "l"(p));
    return a;
}
__device__ __forceinline__ void ldsm_x4t(uint32_t* d, uint32_t addr) {
    asm volatile("ldmatrix.sync.aligned.m8n8.x4.trans.shared.b16 {%0,%1,%2,%3}, [%4];"
        : "=r"(d[0]), "=r"(d[1]), "=r"(d[2]), "=r"(d[3]) : "r"(addr));
}
__device__ __forceinline__ void mma_f16(float* c, const uint32_t* a, uint32_t b0, uint32_t b1) {
    asm volatile(
        "mma.sync.aligned.m16n8k16.row.col.f32.f16.f16.f32 "
        "{%0,%1,%2,%3}, {%4,%5,%6,%7}, {%8,%9}, {%0,%1,%2,%3};"
        : "+f"(c[0]), "+f"(c[1]), "+f"(c[2]), "+f"(c[3])
        : "r"(a[0]), "r"(a[1]), "r"(a[2]), "r"(a[3]), "r"(b0), "r"(b1));
}
__device__ __forceinline__ uint32_t h2u(__half2 h) { return *reinterpret_cast<uint32_t*>(&h); }

// ====================== weight prep (once) ======================
// g_Bh: 128 rows (logical mma-k) x 64 fp16 (=128B/row), 16B chunks XOR-swizzled by (k&7).
// Row k holds W[perm(k)][*] so that A fragments can be built from contiguous float4 loads:
//   logical k in 16-tile: q=k&15, c=(q>>1)&3, e=q&1, hi8=q>>3  ->  physical p = 4c + 2*hi8 + e
__device__ unsigned char g_Bh[128 * 128];

__global__ void prep_weight_kernel(const float* __restrict__ weight) {
    for (int i = threadIdx.x; i < 8192; i += 256) {
        int k = i >> 6, n = i & 63;
        int ks = k >> 4, q = k & 15;
        int c = (q >> 1) & 3, e = q & 1, hi8 = q >> 3;
        int p = 16 * ks + 4 * c + 2 * hi8 + e;          // physical W row (K index)
        __half h = __float2half_rn(weight[p * 64 + n]);
        int chunk = (n >> 3) ^ (k & 7);
        int off = k * 128 + chunk * 16 + (n & 7) * 2;
        *reinterpret_cast<__half*>(g_Bh + off) = h;
    }
}

// ====================== smem layout ======================
// B tile  : 16384 B @ 0 (dead after MMA)
// H       : 128 x 68 fp32 = 34816 B @ 0 (overlays B after barrier)
// w       : 32 blocks x 16 fp32 @ 34816 (2048 B)
// bias    : 64 fp32 @ 36864 (256 B)
#define SM_B    0u
#define SM_H    0u
#define SM_W    34816u
#define SM_BIAS 36864u
#define SMEM_TOTAL 37120
#define H_STRIDE 68

__global__ void __launch_bounds__(256, 3) gcn_f16_kernel(
    const float* __restrict__ feat,
    const float* __restrict__ w,
    const float* __restrict__ bias,
    const float* __restrict__ alpha_p,
    float* __restrict__ out,
    int n_pool_blocks)
{
    extern __shared__ unsigned char s_raw[];
    const uint32_t sb = smem_u32(s_raw);
    const int tid = threadIdx.x;
    const int wid = tid >> 5;
    const int lid = tid & 31;

    const float alpha = __ldg(alpha_p);

    // ---------- copy B tile (16KB), edge weights (2KB), bias ----------
    {
        const uint4* gbp = (const uint4*)&g_Bh[0];
        uint4* sp = (uint4*)(s_raw + SM_B);
        #pragma unroll
        for (int i = 0; i < 4; ++i) sp[tid + i * 256] = gbp[tid + i * 256];
        if (tid < 128) ((uint4*)(s_raw + SM_W))[tid] =
            ((const uint4*)(w + (size_t)blockIdx.x * 512))[tid];
        if (tid < 16)  ((uint4*)(s_raw + SM_BIAS))[tid] = ((const uint4*)bias)[tid];
    }
    __syncthreads();

    // ---------- MMA: warp = 16 rows x 64 cols; K = 2x128 (hi,lo share B) ----------
    float acc[8][4];
    #pragma unroll
    for (int t = 0; t < 8; ++t)
        #pragma unroll
        for (int i = 0; i < 4; ++i) acc[t][i] = 0.f;

    {
        const int c  = lid & 3;
        const int rq = lid >> 2;
        const float* f0 = feat + (size_t)blockIdx.x * (128 * 128)
                        + (size_t)(wid * 16 + rq) * 128 + 4 * c;
        const float* f1 = f0 + 8 * 128;

        const int bKrel = (lid & 7) + ((lid >> 3) & 1) * 8;
        const uint32_t bRow = (uint32_t)bKrel * 128u;
        const int bS  = bKrel & 7;
        const int bC0 = lid >> 4;

        #pragma unroll
        for (int ks = 0; ks < 8; ++ks) {
            float4 F0 = *(const float4*)(f0 + 16 * ks);
            float4 F1 = *(const float4*)(f1 + 16 * ks);

            // hi fragments
            __half2 H0 = __floats2half2_rn(F0.x, F0.y);
            __half2 H1 = __floats2half2_rn(F1.x, F1.y);
            __half2 H2 = __floats2half2_rn(F0.z, F0.w);
            __half2 H3 = __floats2half2_rn(F1.z, F1.w);
            // lo = x - float(hi)
            float2 g0 = __half22float2(H0), g1 = __half22float2(H1);
            float2 g2 = __half22float2(H2), g3 = __half22float2(H3);
            __half2 L0 = __floats2half2_rn(F0.x - g0.x, F0.y - g0.y);
            __half2 L1 = __floats2half2_rn(F1.x - g1.x, F1.y - g1.y);
            __half2 L2 = __floats2half2_rn(F0.z - g2.x, F0.w - g2.y);
            __half2 L3 = __floats2half2_rn(F1.z - g3.x, F1.w - g3.y);
            uint32_t aH[4] = { h2u(H0), h2u(H1), h2u(H2), h2u(H3) };
            uint32_t aL[4] = { h2u(L0), h2u(L1), h2u(L2), h2u(L3) };

            uint32_t b[16];
            const uint32_t bkb = sb + SM_B + (uint32_t)(ks * 2048) + bRow;
            #pragma unroll
            for (int j = 0; j < 4; ++j)
                ldsm_x4t(b + 4 * j, bkb + (uint32_t)((((j << 1) + bC0) ^ bS) << 4));

            #pragma unroll
            for (int ns = 0; ns < 8; ++ns) {
                uint32_t b0 = b[(ns >> 1) * 4 + (ns & 1) * 2];
                uint32_t b1 = b[(ns >> 1) * 4 + (ns & 1) * 2 + 1];
                mma_f16(acc[ns], aH, b0, b1);
                mma_f16(acc[ns], aL, b0, b1);
            }
        }
    }

    __syncthreads();   // all warps done reading B; safe to overlay H

    // ---------- accumulators -> smem H[128][64] (stride 68) ----------
    {
        float* Hp = (float*)(s_raw + SM_H);
        const int row = wid * 16 + (lid >> 2);
        const int cc  = (lid & 3) << 1;
        #pragma unroll
        for (int ns = 0; ns < 8; ++ns) {
            int col = ns * 8 + cc;
            *(float2*)(Hp + (size_t)row * H_STRIDE + col)       = make_float2(acc[ns][0], acc[ns][1]);
            *(float2*)(Hp + (size_t)(row + 8) * H_STRIDE + col) = make_float2(acc[ns][2], acc[ns][3]);
        }
    }
    __syncthreads();

    // ---------- epilogue: 32 node-blocks x 8 threads (8 cols/thread) ----------
    {
        const int tb = tid >> 3;
        const int q  = tid & 7;
        const int c0 = q << 3;
        const float* Hb = (const float*)(s_raw + SM_H);
        const float* ws = (const float*)(s_raw + SM_W) + tb * 16;
        const float* bs = (const float*)(s_raw + SM_BIAS);

        float a0[8], h1[8], h2[8], h3[8], bb[8];
        const float* r0p = Hb + (size_t)(4 * tb    ) * H_STRIDE + c0;
        const float* r1p = Hb + (size_t)(4 * tb + 1) * H_STRIDE + c0;
        const float* r2p = Hb + (size_t)(4 * tb + 2) * H_STRIDE + c0;
        const float* r3p = Hb + (size_t)(4 * tb + 3) * H_STRIDE + c0;
        *(float4*)(a0) = *(const float4*)(r0p); *(float4*)(a0 + 4) = *(const float4*)(r0p + 4);
        *(float4*)(h1) = *(const float4*)(r1p); *(float4*)(h1 + 4) = *(const float4*)(r1p + 4);
        *(float4*)(h2) = *(const float4*)(r2p); *(float4*)(h2 + 4) = *(const float4*)(r2p + 4);
        *(float4*)(h3) = *(const float4*)(r3p); *(float4*)(h3 + 4) = *(const float4*)(r3p + 4);
        *(float4*)(bb) = *(const float4*)(bs + c0); *(float4*)(bb + 4) = *(const float4*)(bs + c0 + 4);

        float pool[8];
        #pragma unroll
        for (int cc = 0; cc < 8; ++cc) pool[cc] = 0.f;
        #pragma unroll
        for (int j = 0; j < 4; ++j) {
            float w1 = ws[4 + j], w2 = ws[8 + j], w3 = ws[12 + j];
            #pragma unroll
            for (int cc = 0; cc < 8; ++cc) {
                float hv = fmaf(w1, h1[cc], fmaf(w2, h2[cc], w3 * h3[cc])) + bb[cc];
                hv = (hv >= 0.f) ? hv : alpha * hv;
                pool[cc] += hv;
            }
        }
        float pn = 0.f, an = 0.f;
        float aa[8];
        #pragma unroll
        for (int cc = 0; cc < 8; ++cc) {
            pool[cc] *= 0.25f;
            pn = fmaf(pool[cc], pool[cc], pn);
            float x = a0[cc] + bb[cc];
            x = (x >= 0.f) ? x : alpha * x;
            aa[cc] = x;
            an = fmaf(x, x, an);
        }
        #pragma unroll
        for (int o = 1; o < 8; o <<= 1) {
            pn += __shfl_xor_sync(0xFFFFFFFFu, pn, o);
            an += __shfl_xor_sync(0xFFFFFFFFu, an, o);
        }
        float pinv = 1.f / fmaxf(sqrtf(pn), 1e-12f);
        float ainv = 1.f / fmaxf(sqrtf(an), 1e-12f);

        size_t gb = (size_t)blockIdx.x * 32 + tb;
        float* po = out + gb * 64 + c0;
        float* ao = out + (size_t)n_pool_blocks * 64 + gb * 64 + c0;
        *(float4*)(po)     = make_float4(pool[0]*pinv, pool[1]*pinv, pool[2]*pinv, pool[3]*pinv);
        *(float4*)(po + 4) = make_float4(pool[4]*pinv, pool[5]*pinv, pool[6]*pinv, pool[7]*pinv);
        *(float4*)(ao)     = make_float4(aa[0]*ainv, aa[1]*ainv, aa[2]*ainv, aa[3]*ainv);
        *(float4*)(ao + 4) = make_float4(aa[4]*ainv, aa[5]*ainv, aa[6]*ainv, aa[7]*ainv);
    }
}

extern "C" void kernel_launch(void* const* d_in, const int* in_sizes, int n_in,
                              void* d_out, int out_size) {
    const float* feat   = (const float*)d_in[0];
    const float* w      = (const float*)d_in[1];
    const float* weight = (const float*)d_in[2];
    const float* bias   = (const float*)d_in[3];
    const float* alpha  = (const float*)d_in[4];
    float* out = (float*)d_out;

    int n_nodes = in_sizes[0] / 128;       // N = 524288
    int n_blk   = n_nodes / 4;             // B = 131072
    int grid    = n_nodes / 128;           // 4096 CTAs

    prep_weight_kernel<<<1, 256>>>(weight);

    cudaFuncSetAttribute(gcn_f16_kernel,
                         cudaFuncAttributeMaxDynamicSharedMemorySize, SMEM_TOTAL);
    gcn_f16_kernel<<<grid, 256, SMEM_TOTAL>>>(feat, w, bias, alpha, out, n_blk);
}

// round 5
// speedup vs baseline: 2.7768x; 1.0047x over previous
#include <cuda_runtime.h>
#include <cuda_fp16.h>
#include <cstdint>

// ====================== helpers ======================
__device__ __forceinline__ uint32_t smem_u32(const void* p) {
    uint32_t a;
    asm("{ .reg .u64 t; cvta.to.shared.u64 t, %1; cvt.u32.u64 %0, t; }" : "=r"(a) : "l"(p));
    return a;
}
__device__ __forceinline__ void ldsm_x4t(uint32_t* d, uint32_t addr) {
    asm volatile("ldmatrix.sync.aligned.m8n8.x4.trans.shared.b16 {%0,%1,%2,%3}, [%4];"
        : "=r"(d[0]), "=r"(d[1]), "=r"(d[2]), "=r"(d[3]) : "r"(addr));
}
__device__ __forceinline__ void mma_f16(float* c, const uint32_t* a, uint32_t b0, uint32_t b1) {
    asm volatile(
        "mma.sync.aligned.m16n8k16.row.col.f32.f16.f16.f32 "
        "{%0,%1,%2,%3}, {%4,%5,%6,%7}, {%8,%9}, {%0,%1,%2,%3};"
        : "+f"(c[0]), "+f"(c[1]), "+f"(c[2]), "+f"(c[3])
        : "r"(a[0]), "r"(a[1]), "r"(a[2]), "r"(a[3]), "r"(b0), "r"(b1));
}
__device__ __forceinline__ uint32_t h2u(__half2 h) { return *reinterpret_cast<uint32_t*>(&h); }

// ====================== weight prep (once) ======================
// g_Bh: 128 rows (logical mma-k) x 64 fp16 (=128B/row), 16B chunks XOR-swizzled by (k&7).
// Row k holds W[perm(k)][*]:  q=k&15, c=(q>>1)&3, e=q&1, hi8=q>>3 -> p = 16*(k>>4)+4c+2*hi8+e
__device__ unsigned char g_Bh[128 * 128];

__global__ void prep_weight_kernel(const float* __restrict__ weight) {
    int i = blockIdx.x * 256 + threadIdx.x;
    if (i < 8192) {
        int k = i >> 6, n = i & 63;
        int ks = k >> 4, q = k & 15;
        int c = (q >> 1) & 3, e = q & 1, hi8 = q >> 3;
        int p = 16 * ks + 4 * c + 2 * hi8 + e;
        __half h = __float2half_rn(weight[p * 64 + n]);
        int chunk = (n >> 3) ^ (k & 7);
        int off = k * 128 + chunk * 16 + (n & 7) * 2;
        *reinterpret_cast<__half*>(g_Bh + off) = h;
    }
}

// ====================== smem layout ======================
#define SM_B    0u
#define SM_W    16384u
#define SM_BIAS 18432u
#define SMEM_TOTAL 18688

__global__ void __launch_bounds__(256, 3) gcn_f16_kernel(
    const float* __restrict__ feat,
    const float* __restrict__ w,
    const float* __restrict__ bias,
    const float* __restrict__ alpha_p,
    float* __restrict__ out,
    int n_pool_blocks)
{
    extern __shared__ unsigned char s_raw[];
    const uint32_t sb = smem_u32(s_raw);
    const int tid = threadIdx.x;
    const int wid = tid >> 5;
    const int lid = tid & 31;

    const float alpha = __ldg(alpha_p);

    // ---------- stage B tile (16KB), edge weights (2KB), bias ----------
    {
        const uint4* gbp = (const uint4*)&g_Bh[0];
        uint4* sp = (uint4*)(s_raw + SM_B);
        #pragma unroll
        for (int i = 0; i < 4; ++i) sp[tid + i * 256] = gbp[tid + i * 256];
        if (tid < 128) ((uint4*)(s_raw + SM_W))[tid] =
            ((const uint4*)(w + (size_t)blockIdx.x * 512))[tid];
        if (tid < 16)  ((uint4*)(s_raw + SM_BIAS))[tid] = ((const uint4*)bias)[tid];
    }
    __syncthreads();

    // ---------- MMA: warp = 16 rows x 64 cols; K = 2x128 (hi,lo share B frags) ----------
    float acc[8][4];
    #pragma unroll
    for (int t = 0; t < 8; ++t)
        #pragma unroll
        for (int i = 0; i < 4; ++i) acc[t][i] = 0.f;

    {
        const int c  = lid & 3;
        const int rq = lid >> 2;
        const float* f0 = feat + (size_t)blockIdx.x * (128 * 128)
                        + (size_t)(wid * 16 + rq) * 128 + 4 * c;
        const float* f1 = f0 + 8 * 128;

        const int bKrel = (lid & 7) + ((lid >> 3) & 1) * 8;
        const uint32_t bRow = (uint32_t)bKrel * 128u;
        const int bS  = bKrel & 7;
        const int bC0 = lid >> 4;

        #pragma unroll
        for (int ks = 0; ks < 8; ++ks) {
            float4 F0 = *(const float4*)(f0 + 16 * ks);
            float4 F1 = *(const float4*)(f1 + 16 * ks);

            __half2 H0 = __floats2half2_rn(F0.x, F0.y);
            __half2 H1 = __floats2half2_rn(F1.x, F1.y);
            __half2 H2 = __floats2half2_rn(F0.z, F0.w);
            __half2 H3 = __floats2half2_rn(F1.z, F1.w);
            float2 g0 = __half22float2(H0), g1 = __half22float2(H1);
            float2 g2 = __half22float2(H2), g3 = __half22float2(H3);
            __half2 L0 = __floats2half2_rn(F0.x - g0.x, F0.y - g0.y);
            __half2 L1 = __floats2half2_rn(F1.x - g1.x, F1.y - g1.y);
            __half2 L2 = __floats2half2_rn(F0.z - g2.x, F0.w - g2.y);
            __half2 L3 = __floats2half2_rn(F1.z - g3.x, F1.w - g3.y);
            uint32_t aH[4] = { h2u(H0), h2u(H1), h2u(H2), h2u(H3) };
            uint32_t aL[4] = { h2u(L0), h2u(L1), h2u(L2), h2u(L3) };

            uint32_t b[16];
            const uint32_t bkb = sb + SM_B + (uint32_t)(ks * 2048) + bRow;
            #pragma unroll
            for (int j = 0; j < 4; ++j)
                ldsm_x4t(b + 4 * j, bkb + (uint32_t)((((j << 1) + bC0) ^ bS) << 4));

            #pragma unroll
            for (int ns = 0; ns < 8; ++ns) {
                uint32_t b0 = b[(ns >> 1) * 4 + (ns & 1) * 2];
                uint32_t b1 = b[(ns >> 1) * 4 + (ns & 1) * 2 + 1];
                mma_f16(acc[ns], aH, b0, b1);
                mma_f16(acc[ns], aL, b0, b1);
            }
        }
    }

    // ---------- in-register epilogue (no smem H, no extra barriers) ----------
    {
        const float* wsm = (const float*)(s_raw + SM_W);
        const float* bsm = (const float*)(s_raw + SM_BIAS);
        const int q  = lid & 3;
        const int i  = (lid >> 2) & 3;          // row within node-block
        const int bq = (lid >> 4) & 1;
        const int srcBase = lid & 0x13;         // keep q + bq bits

        #pragma unroll
        for (int h = 0; h < 2; ++h) {
            const int b_cta = wid * 4 + 2 * h + bq;
            const float* wb = wsm + b_cta * 16;

            // this lane's row values (16 cols) for fragment half h
            float v[16];
            #pragma unroll
            for (int ns = 0; ns < 8; ++ns) {
                v[2 * ns]     = acc[ns][2 * h];
                v[2 * ns + 1] = acc[ns][2 * h + 1];
            }

            // h_pre = bias + sum_s w[b][s][i] * v_s  (sources s = 1..3 via shfl)
            float hp[16];
            #pragma unroll
            for (int ns = 0; ns < 8; ++ns) {
                float2 bv = *(const float2*)(bsm + ns * 8 + q * 2);
                hp[2 * ns] = bv.x; hp[2 * ns + 1] = bv.y;
            }
            #pragma unroll
            for (int s = 1; s <= 3; ++s) {
                int sl = srcBase | (s << 2);
                float wsj = wb[s * 4 + i];
                #pragma unroll
                for (int c = 0; c < 16; ++c)
                    hp[c] = fmaf(wsj, __shfl_sync(0xFFFFFFFFu, v[c], sl), hp[c]);
            }

            // prelu, then mean over the 4 destinations (butterfly over i bits)
            #pragma unroll
            for (int c = 0; c < 16; ++c)
                hp[c] = (hp[c] >= 0.f) ? hp[c] : alpha * hp[c];
            #pragma unroll
            for (int c = 0; c < 16; ++c) hp[c] += __shfl_xor_sync(0xFFFFFFFFu, hp[c], 4);
            #pragma unroll
            for (int c = 0; c < 16; ++c) hp[c] += __shfl_xor_sync(0xFFFFFFFFu, hp[c], 8);

            // norms: pool (all lanes) + anchor (valid on i==0 lanes)
            float pn = 0.f, an = 0.f;
            #pragma unroll
            for (int c = 0; c < 16; ++c) {
                float p = hp[c] * 0.25f;
                hp[c] = p;
                pn = fmaf(p, p, pn);
                float2 bv = *(const float2*)(bsm + (c >> 1) * 8 + q * 2);
                float x = v[c] + ((c & 1) ? bv.y : bv.x);
                x = (x >= 0.f) ? x : alpha * x;
                an = fmaf(x, x, an);
            }
            pn += __shfl_xor_sync(0xFFFFFFFFu, pn, 1);
            pn += __shfl_xor_sync(0xFFFFFFFFu, pn, 2);
            an += __shfl_xor_sync(0xFFFFFFFFu, an, 1);
            an += __shfl_xor_sync(0xFFFFFFFFu, an, 2);
            float pinv = 1.f / fmaxf(sqrtf(pn), 1e-12f);
            float ainv = 1.f / fmaxf(sqrtf(an), 1e-12f);

            if (i == 0) {
                size_t gb = (size_t)blockIdx.x * 32 + b_cta;
                float* po = out + gb * 64 + q * 2;
                float* ao = out + (size_t)n_pool_blocks * 64 + gb * 64 + q * 2;
                #pragma unroll
                for (int ns = 0; ns < 8; ++ns) {
                    *(float2*)(po + ns * 8) =
                        make_float2(hp[2 * ns] * pinv, hp[2 * ns + 1] * pinv);
                    float2 bv = *(const float2*)(bsm + ns * 8 + q * 2);
                    float x0 = v[2 * ns]     + bv.x;
                    float x1 = v[2 * ns + 1] + bv.y;
                    x0 = (x0 >= 0.f) ? x0 : alpha * x0;
                    x1 = (x1 >= 0.f) ? x1 : alpha * x1;
                    *(float2*)(ao + ns * 8) = make_float2(x0 * ainv, x1 * ainv);
                }
            }
        }
    }
}

extern "C" void kernel_launch(void* const* d_in, const int* in_sizes, int n_in,
                              void* d_out, int out_size) {
    const float* feat   = (const float*)d_in[0];
    const float* w      = (const float*)d_in[1];
    const float* weight = (const float*)d_in[2];
    const float* bias   = (const float*)d_in[3];
    const float* alpha  = (const float*)d_in[4];
    float* out = (float*)d_out;

    int n_nodes = in_sizes[0] / 128;       // N = 524288
    int n_blk   = n_nodes / 4;             // B = 131072
    int grid    = n_nodes / 128;           // 4096 CTAs

    prep_weight_kernel<<<32, 256>>>(weight);

    cudaFuncSetAttribute(gcn_f16_kernel,
                         cudaFuncAttributeMaxDynamicSharedMemorySize, SMEM_TOTAL);
    gcn_f16_kernel<<<grid, 256, SMEM_TOTAL>>>(feat, w, bias, alpha, out, n_blk);
}